// round 1
// baseline (speedup 1.0000x reference)
#include <cuda_runtime.h>
#include <math.h>
#include <stdint.h>

// ---------------- problem constants ----------------
#define NB       512          // graphs
#define PP       64           // nodes per graph
#define NN       (NB*PP)      // 32768 nodes
#define FF       128          // input feature dim
#define HH       256          // hidden dim
#define KSORT    30
#define KCONV    4
#define LOUT     27           // KSORT-KCONV+1
#define MCONV    (NB*LOUT)    // 13824
#define KIM      (HH*KCONV)   // 1024

// ---------------- static scratch (no cudaMalloc allowed) ----------------
__device__ float g_A   [NB*PP*PP];        // 8MB normalized adjacency
__device__ float g_hA  [NN*HH];
__device__ float g_hB  [NN*HH];
__device__ float g_HL  [NN*HH];
__device__ float g_HR  [NN*HH];
__device__ float g_topk[NB*KSORT*HH];
__device__ float g_im  [MCONV*KIM];       // 56MB im2col
__device__ float g_Wr  [KIM*HH];          // reshaped conv weight
__device__ float g_yc  [MCONV*HH];        // conv output [(g,t), o]
__device__ float g_z1  [NB*HH];           // lin1 split-K accumulator

// ---------------- small utility kernels ----------------
__global__ void zero_f(float* p, int n) {
    int i = blockIdx.x * 256 + threadIdx.x;
    if (i < n) p[i] = 0.f;
}

__global__ void nan_copy(const float* __restrict__ x, float* __restrict__ h, int n) {
    int i = blockIdx.x * 256 + threadIdx.x;
    if (i < n) { float v = x[i]; h[i] = isnan(v) ? 0.f : v; }
}

__global__ void build_adj(const int* __restrict__ src, const int* __restrict__ dst,
                          int E, float* __restrict__ A) {
    int e = blockIdx.x * 256 + threadIdx.x;
    if (e >= E) return;
    int s = src[e], d = dst[e];
    int g = d >> 6;
    atomicAdd(&A[((size_t)g << 12) + ((size_t)(d & 63) << 6) + (s & 63)], 1.0f);
}

// row-normalize A by 1/max(deg,1); one warp per 64-wide row
__global__ void norm_adj(float* __restrict__ A) {
    int row  = blockIdx.x * 8 + (threadIdx.x >> 5);
    int lane = threadIdx.x & 31;
    float* rp = A + (size_t)row * 64;
    float v0 = rp[lane], v1 = rp[lane + 32];
    float s = v0 + v1;
    #pragma unroll
    for (int o = 16; o > 0; o >>= 1) s += __shfl_xor_sync(0xffffffffu, s, o);
    float inv = 1.f / fmaxf(s, 1.f);
    rp[lane] = v0 * inv; rp[lane + 32] = v1 * inv;
}

// Wr[(s*256+i)][o] = conv1d_w[o][i][s]
__global__ void build_wr(const float* __restrict__ w, float* __restrict__ Wr) {
    int idx = blockIdx.x * 256 + threadIdx.x;
    if (idx >= KIM * HH) return;
    int o = idx & 255;
    int k = idx >> 8;
    int s = k >> 8;
    int i = k & 255;
    Wr[idx] = w[((size_t)(o * 256 + i)) * 4 + s];
}

// ---------------- main fp32 GEMM: C[M,N] = A[M,K] @ B[K,N] (+bias, relu) ----
// BM=BN=128, BK=16, 256 threads, 8x8 per thread. M%128==0, N%128==0, K%16==0.
__global__ __launch_bounds__(256) void gemm_f32(
    const float* __restrict__ A, const float* __restrict__ B,
    float* __restrict__ C, int M, int N, int K,
    const float* __restrict__ bias, int do_relu)
{
    __shared__ float As[16][128];
    __shared__ float Bs[16][128];
    int t  = threadIdx.x;
    int bn = blockIdx.x, bm = blockIdx.y;
    int tx = t & 15, ty = t >> 4;
    const float* Ab = A + (size_t)bm * 128 * K;
    const float* Bb = B + (size_t)bn * 128;

    float acc[8][8];
    #pragma unroll
    for (int i = 0; i < 8; i++)
        #pragma unroll
        for (int j = 0; j < 8; j++) acc[i][j] = 0.f;

    for (int kt = 0; kt < K; kt += 16) {
        #pragma unroll
        for (int h = 0; h < 2; h++) {
            int idx = t + h * 256;               // 0..511 (float4 slots)
            int row = idx >> 2, c4 = (idx & 3) * 4;
            float4 v = *reinterpret_cast<const float4*>(Ab + (size_t)row * K + kt + c4);
            As[c4 + 0][row] = v.x; As[c4 + 1][row] = v.y;
            As[c4 + 2][row] = v.z; As[c4 + 3][row] = v.w;
        }
        #pragma unroll
        for (int h = 0; h < 2; h++) {
            int idx = t + h * 256;
            int row = idx >> 5, c4 = (idx & 31) * 4;
            float4 v = *reinterpret_cast<const float4*>(Bb + (size_t)(kt + row) * N + c4);
            *reinterpret_cast<float4*>(&Bs[row][c4]) = v;
        }
        __syncthreads();
        #pragma unroll
        for (int k = 0; k < 16; k++) {
            float a[8], b[8];
            *reinterpret_cast<float4*>(&a[0]) = *reinterpret_cast<const float4*>(&As[k][ty * 8]);
            *reinterpret_cast<float4*>(&a[4]) = *reinterpret_cast<const float4*>(&As[k][ty * 8 + 4]);
            *reinterpret_cast<float4*>(&b[0]) = *reinterpret_cast<const float4*>(&Bs[k][tx * 8]);
            *reinterpret_cast<float4*>(&b[4]) = *reinterpret_cast<const float4*>(&Bs[k][tx * 8 + 4]);
            #pragma unroll
            for (int i = 0; i < 8; i++)
                #pragma unroll
                for (int j = 0; j < 8; j++) acc[i][j] += a[i] * b[j];
        }
        __syncthreads();
    }
    #pragma unroll
    for (int i = 0; i < 8; i++) {
        int m = bm * 128 + ty * 8 + i;
        float* Crow = C + (size_t)m * N + bn * 128 + tx * 8;
        #pragma unroll
        for (int j = 0; j < 8; j++) {
            float v = acc[i][j];
            if (bias) v += bias[bn * 128 + tx * 8 + j];
            if (do_relu) v = fmaxf(v, 0.f);
            Crow[j] = v;
        }
    }
}

// ------------- SAGE combine: Hout = relu(A_g @ HL_g + b + HR_g) -------------
// one block per graph; smem: adj (transposed) 16KB + HL half-tile 32KB = 48KB
__global__ __launch_bounds__(256) void sage_combine(
    const float* __restrict__ HL, const float* __restrict__ HR,
    const float* __restrict__ bias, float* __restrict__ Hout,
    const float* __restrict__ Aadj)
{
    __shared__ float As[64][64];     // As[k][n] = A_g[n][k]
    __shared__ float HLs[64][128];
    int g = blockIdx.x, t = threadIdx.x;
    const float* Ag = Aadj + ((size_t)g << 12);

    #pragma unroll
    for (int h = 0; h < 4; h++) {
        int idx = t + h * 256;                 // 0..1023 float4 slots
        int n = idx >> 4, k4 = (idx & 15) * 4;
        float4 v = *reinterpret_cast<const float4*>(Ag + (size_t)n * 64 + k4);
        As[k4 + 0][n] = v.x; As[k4 + 1][n] = v.y;
        As[k4 + 2][n] = v.z; As[k4 + 3][n] = v.w;
    }

    int ngrp = t >> 4;     // 0..15  -> n0 = ngrp*4
    int cgrp = t & 15;     // 0..15  -> c0 = cgrp*8 (within 128-col chunk)

    for (int ch = 0; ch < 2; ch++) {
        __syncthreads();   // protect As (first iter) / HLs reuse (second iter)
        #pragma unroll
        for (int h = 0; h < 8; h++) {
            int idx = t + h * 256;             // 0..2047 float4 slots
            int k = idx >> 5, c4 = (idx & 31) * 4;
            *reinterpret_cast<float4*>(&HLs[k][c4]) =
                *reinterpret_cast<const float4*>(HL + ((size_t)(g * 64 + k)) * HH + ch * 128 + c4);
        }
        __syncthreads();

        float acc[4][8];
        #pragma unroll
        for (int i = 0; i < 4; i++)
            #pragma unroll
            for (int j = 0; j < 8; j++) acc[i][j] = 0.f;

        #pragma unroll 4
        for (int k = 0; k < 64; k++) {
            float a[4], b[8];
            *reinterpret_cast<float4*>(&a[0]) = *reinterpret_cast<const float4*>(&As[k][ngrp * 4]);
            *reinterpret_cast<float4*>(&b[0]) = *reinterpret_cast<const float4*>(&HLs[k][cgrp * 8]);
            *reinterpret_cast<float4*>(&b[4]) = *reinterpret_cast<const float4*>(&HLs[k][cgrp * 8 + 4]);
            #pragma unroll
            for (int i = 0; i < 4; i++)
                #pragma unroll
                for (int j = 0; j < 8; j++) acc[i][j] += a[i] * b[j];
        }
        #pragma unroll
        for (int i = 0; i < 4; i++) {
            int n = ngrp * 4 + i;
            size_t base = ((size_t)(g * 64 + n)) * HH + ch * 128 + cgrp * 8;
            #pragma unroll
            for (int j = 0; j < 8; j++) {
                float v = acc[i][j] + bias[ch * 128 + cgrp * 8 + j] + HR[base + j];
                Hout[base + j] = fmaxf(v, 0.f);
            }
        }
    }
}

// ------------- SortPool: rank by channel 255 desc (stable), copy top-30 -----
__global__ __launch_bounds__(256) void sort_topk(
    const float* __restrict__ H, float* __restrict__ topk)
{
    int g = blockIdx.x, t = threadIdx.x;
    __shared__ float keys[64];
    __shared__ int   sel[KSORT];
    if (t < 64) keys[t] = H[((size_t)(g * 64 + t)) * HH + 255];
    __syncthreads();
    if (t < 64) {
        float kv = keys[t];
        int r = 0;
        #pragma unroll
        for (int m = 0; m < 64; m++) {
            float km = keys[m];
            r += (km > kv) || (km == kv && m < t);
        }
        if (r < KSORT) sel[r] = t;
    }
    __syncthreads();
    for (int idx = t; idx < KSORT * HH; idx += 256) {
        int r = idx >> 8, c = idx & 255;
        topk[(size_t)g * KSORT * HH + idx] = H[((size_t)(g * 64 + sel[r])) * HH + c];
    }
}

// ------------- im2col for conv1d (float4 granularity) ------------------------
__global__ void im2col_k(const float* __restrict__ topk, float* __restrict__ X)
{
    int idx = blockIdx.x * 256 + threadIdx.x;          // float4 index
    if (idx >= MCONV * (KIM / 4)) return;
    int c4 = idx & 255;            // float4 within 1024-row
    int s  = c4 >> 6;              // kernel tap
    int i4 = c4 & 63;              // float4 within 256 channels
    int m  = idx >> 8;
    int tp = m % LOUT;
    int g  = m / LOUT;
    const float4* tk4 = reinterpret_cast<const float4*>(topk);
    reinterpret_cast<float4*>(X)[idx] =
        tk4[(size_t)g * (KSORT * HH / 4) + (tp + s) * (HH / 4) + i4];
}

// ------------- lin1 split-K GEMM with strided A/B, fp32 atomics -------------
// Z[g,c] += sum_o Y[(g*27+ts)*256+o] * W1[(o*27+ts)*256+c], grid (2,4,27)
__global__ __launch_bounds__(256) void lin1_splitk(
    const float* __restrict__ Y, const float* __restrict__ W1,
    float* __restrict__ Zacc)
{
    __shared__ float As[16][128];
    __shared__ float Bs[16][128];
    int t  = threadIdx.x;
    int bn = blockIdx.x, bm = blockIdx.y, ts = blockIdx.z;
    int tx = t & 15, ty = t >> 4;

    float acc[8][8];
    #pragma unroll
    for (int i = 0; i < 8; i++)
        #pragma unroll
        for (int j = 0; j < 8; j++) acc[i][j] = 0.f;

    for (int kt = 0; kt < 256; kt += 16) {
        #pragma unroll
        for (int h = 0; h < 2; h++) {
            int idx = t + h * 256;
            int row = idx >> 2, c4 = (idx & 3) * 4;
            float4 v = *reinterpret_cast<const float4*>(
                Y + ((size_t)(bm * 128 + row) * LOUT + ts) * HH + kt + c4);
            As[c4 + 0][row] = v.x; As[c4 + 1][row] = v.y;
            As[c4 + 2][row] = v.z; As[c4 + 3][row] = v.w;
        }
        #pragma unroll
        for (int h = 0; h < 2; h++) {
            int idx = t + h * 256;
            int row = idx >> 5, c4 = (idx & 31) * 4;
            float4 v = *reinterpret_cast<const float4*>(
                W1 + ((size_t)(kt + row) * LOUT + ts) * HH + bn * 128 + c4);
            *reinterpret_cast<float4*>(&Bs[row][c4]) = v;
        }
        __syncthreads();
        #pragma unroll
        for (int k = 0; k < 16; k++) {
            float a[8], b[8];
            *reinterpret_cast<float4*>(&a[0]) = *reinterpret_cast<const float4*>(&As[k][ty * 8]);
            *reinterpret_cast<float4*>(&a[4]) = *reinterpret_cast<const float4*>(&As[k][ty * 8 + 4]);
            *reinterpret_cast<float4*>(&b[0]) = *reinterpret_cast<const float4*>(&Bs[k][tx * 8]);
            *reinterpret_cast<float4*>(&b[4]) = *reinterpret_cast<const float4*>(&Bs[k][tx * 8 + 4]);
            #pragma unroll
            for (int i = 0; i < 8; i++)
                #pragma unroll
                for (int j = 0; j < 8; j++) acc[i][j] += a[i] * b[j];
        }
        __syncthreads();
    }
    #pragma unroll
    for (int i = 0; i < 8; i++) {
        int m = bm * 128 + ty * 8 + i;
        #pragma unroll
        for (int j = 0; j < 8; j++)
            atomicAdd(&Zacc[(size_t)m * HH + bn * 128 + tx * 8 + j], acc[i][j]);
    }
}

// ------------- final MLP: relu(z1+b1) -> relu(@W2+b2) -> relu(@W3+b3) -------
__global__ __launch_bounds__(256) void mlp_kernel(
    const float* __restrict__ z1acc, const float* __restrict__ b1,
    const float* __restrict__ W2,   const float* __restrict__ b2,
    const float* __restrict__ W3,   const float* __restrict__ b3,
    float* __restrict__ out)
{
    int g = blockIdx.x, t = threadIdx.x;
    __shared__ float s1[256];
    __shared__ float s2[128];
    s1[t] = fmaxf(z1acc[(size_t)g * 256 + t] + b1[t], 0.f);
    __syncthreads();
    if (t < 128) {
        float acc = b2[t];
        #pragma unroll 8
        for (int k = 0; k < 256; k++) acc += s1[k] * W2[(size_t)k * 128 + t];
        s2[t] = fmaxf(acc, 0.f);
    }
    __syncthreads();
    if (t < 10) {
        float acc = b3[t];
        #pragma unroll
        for (int k = 0; k < 128; k++) acc += s2[k] * W3[(size_t)k * 10 + t];
        out[(size_t)g * 10 + t] = fmaxf(acc, 0.f);
    }
}

// ---------------- launch ----------------
extern "C" void kernel_launch(void* const* d_in, const int* in_sizes, int n_in,
                              void* d_out, int out_size)
{
    const float* x    = (const float*)d_in[0];
    const int*   ei   = (const int*)  d_in[1];
    int E = in_sizes[1] / 2;
    const int* src = ei;
    const int* dst = ei + E;

    const float* wl[4] = {(const float*)d_in[3], (const float*)d_in[6],
                          (const float*)d_in[9], (const float*)d_in[12]};
    const float* wr[4] = {(const float*)d_in[4], (const float*)d_in[7],
                          (const float*)d_in[10], (const float*)d_in[13]};
    const float* sb[4] = {(const float*)d_in[5], (const float*)d_in[8],
                          (const float*)d_in[11], (const float*)d_in[14]};
    const float* convw = (const float*)d_in[15];
    const float* convb = (const float*)d_in[16];
    const float* l1w   = (const float*)d_in[17];
    const float* l1b   = (const float*)d_in[18];
    const float* l2w   = (const float*)d_in[19];
    const float* l2b   = (const float*)d_in[20];
    const float* ow    = (const float*)d_in[21];
    const float* ob    = (const float*)d_in[22];

    float *pA, *phA, *phB, *pHL, *pHR, *ptopk, *pim, *pWr, *pyc, *pz1;
    cudaGetSymbolAddress((void**)&pA,    g_A);
    cudaGetSymbolAddress((void**)&phA,   g_hA);
    cudaGetSymbolAddress((void**)&phB,   g_hB);
    cudaGetSymbolAddress((void**)&pHL,   g_HL);
    cudaGetSymbolAddress((void**)&pHR,   g_HR);
    cudaGetSymbolAddress((void**)&ptopk, g_topk);
    cudaGetSymbolAddress((void**)&pim,   g_im);
    cudaGetSymbolAddress((void**)&pWr,   g_Wr);
    cudaGetSymbolAddress((void**)&pyc,   g_yc);
    cudaGetSymbolAddress((void**)&pz1,   g_z1);

    // preprocessing
    zero_f<<<(NB*PP*PP + 255)/256, 256>>>(pA, NB*PP*PP);
    build_adj<<<(E + 255)/256, 256>>>(src, dst, E, pA);
    norm_adj<<<NN/8, 256>>>(pA);
    nan_copy<<<(NN*FF + 255)/256, 256>>>(x, phA, NN*FF);
    build_wr<<<(KIM*HH + 255)/256, 256>>>(convw, pWr);
    zero_f<<<(NB*HH + 255)/256, 256>>>(pz1, NB*HH);

    // 4 SAGE layers
    float* hc = phA;
    float* hn = phB;
    for (int l = 0; l < 4; l++) {
        int K = (l == 0) ? FF : HH;
        gemm_f32<<<dim3(HH/128, NN/128), 256>>>(hc, wl[l], pHL, NN, HH, K, nullptr, 0);
        gemm_f32<<<dim3(HH/128, NN/128), 256>>>(hc, wr[l], pHR, NN, HH, K, nullptr, 0);
        sage_combine<<<NB, 256>>>(pHL, pHR, sb[l], hn, pA);
        float* tmp = hc; hc = hn; hn = tmp;
    }

    // SortPool + conv1d (as GEMM) + MLP head
    sort_topk<<<NB, 256>>>(hc, ptopk);
    im2col_k<<<(MCONV*(KIM/4) + 255)/256, 256>>>(ptopk, pim);
    gemm_f32<<<dim3(HH/128, MCONV/128), 256>>>(pim, pWr, pyc, MCONV, HH, KIM, convb, 1);
    lin1_splitk<<<dim3(2, 4, LOUT), 256>>>(pyc, l1w, pz1);
    mlp_kernel<<<NB, 256>>>(pz1, l1b, l2w, l2b, ow, ob, (float*)d_out);
}

// round 5
// speedup vs baseline: 1.3207x; 1.3207x over previous
#include <cuda_runtime.h>
#include <cuda_bf16.h>
#include <math.h>
#include <stdint.h>

// ---------------- problem constants ----------------
#define NB       512
#define PP       64
#define NN       (NB*PP)      // 32768
#define FF       128
#define HH       256
#define KSORT    30
#define LOUT     27
#define MCONV    (NB*LOUT)    // 13824 = 108*128

// ---------------- static scratch ----------------
__device__ __align__(16) float g_A  [NB*PP*PP];   // normalized adjacency
__device__ __align__(16) float g_h0 [NN*HH];      // activations ping
__device__ __align__(16) float g_h1 [NN*HH];      // pong
__device__ __align__(16) float g_HL [NN*HH];
__device__ __align__(16) float g_HR [NN*HH];
__device__ __align__(16) float g_yc [MCONV*HH];
__device__ __align__(16) float g_z1 [NB*HH];
// bf16 split planes (conv path only — not key-relevant)
__device__ __align__(16) __nv_bfloat16 g_t0[NB*KSORT*HH], g_t1[NB*KSORT*HH];
__device__ __align__(16) __nv_bfloat16 g_c0[HH*1024],     g_c1[HH*1024];

// ---------------- helpers ----------------
__device__ __forceinline__ uint32_t smem_u32(const void* p) {
    uint32_t a;
    asm("{ .reg .u64 t; cvta.to.shared.u64 t, %1; cvt.u32.u64 %0, t; }" : "=r"(a) : "l"(p));
    return a;
}
__device__ __forceinline__ void cpasync16(uint32_t dst, const void* src) {
    asm volatile("cp.async.cg.shared.global [%0], [%1], 16;" :: "r"(dst), "l"(src));
}
__device__ __forceinline__ void mma16(float* d, uint32_t a0, uint32_t a1,
                                      uint32_t a2, uint32_t a3,
                                      uint32_t b0, uint32_t b1) {
    asm volatile(
        "mma.sync.aligned.m16n8k16.row.col.f32.bf16.bf16.f32 "
        "{%0,%1,%2,%3}, {%4,%5,%6,%7}, {%8,%9}, {%0,%1,%2,%3};"
        : "+f"(d[0]), "+f"(d[1]), "+f"(d[2]), "+f"(d[3])
        : "r"(a0), "r"(a1), "r"(a2), "r"(a3), "r"(b0), "r"(b1));
}

// ============ SAGE GEMM: bit-identical FP order to R1, better pipeline ======
// C[M,256] = A[M,K] @ B[K,256]. BM=BN=128, BK=16, 256 thr, 8x8/thread.
// FP sequence per output: acc += a*b for k ascending (chunks ascending) —
// identical to the round-1 kernel that passed. Only scheduling differs.
__global__ __launch_bounds__(256) void gemm_f32ex(
    const float* __restrict__ A, const float* __restrict__ B,
    float* __restrict__ C, int K)
{
    __shared__ float As[2][16][128];
    __shared__ float Bs[2][16][128];
    const int t  = threadIdx.x;
    const int bn = blockIdx.x, bm = blockIdx.y;
    const int tx = t & 15, ty = t >> 4;
    const float* Ab = A + (size_t)bm * 128 * K;
    const float* Bb = B + bn * 128;
    const int nch = K >> 4;

    int arow[2], ak4[2], brow[2], bc4[2];
    #pragma unroll
    for (int h = 0; h < 2; h++) {
        int idx = t + h * 256;
        arow[h] = idx >> 2;  ak4[h] = (idx & 3) * 4;
        brow[h] = idx >> 5;  bc4[h] = (idx & 31) * 4;
    }
    uint32_t sBs = smem_u32(Bs);

    // prefetch A chunk 0 into regs; cp.async B chunk 0 into stage 0
    float4 apref[2];
    #pragma unroll
    for (int h = 0; h < 2; h++)
        apref[h] = *(const float4*)(Ab + (size_t)arow[h] * K + ak4[h]);
    #pragma unroll
    for (int h = 0; h < 2; h++)
        cpasync16(sBs + (uint32_t)((brow[h] * 128 + bc4[h]) * 4),
                  Bb + (size_t)brow[h] * 256 + bc4[h]);
    asm volatile("cp.async.commit_group;" ::: "memory");

    float acc[8][8];
    #pragma unroll
    for (int i = 0; i < 8; i++)
        #pragma unroll
        for (int j = 0; j < 8; j++) acc[i][j] = 0.f;

    for (int c = 0; c < nch; c++) {
        const int st = c & 1;
        // stage A chunk c into smem (transposed)
        #pragma unroll
        for (int h = 0; h < 2; h++) {
            As[st][ak4[h] + 0][arow[h]] = apref[h].x;
            As[st][ak4[h] + 1][arow[h]] = apref[h].y;
            As[st][ak4[h] + 2][arow[h]] = apref[h].z;
            As[st][ak4[h] + 3][arow[h]] = apref[h].w;
        }
        // prefetch A chunk c+1
        if (c + 1 < nch) {
            #pragma unroll
            for (int h = 0; h < 2; h++)
                apref[h] = *(const float4*)(Ab + (size_t)arow[h] * K + (c + 1) * 16 + ak4[h]);
        }
        asm volatile("cp.async.wait_group 0;" ::: "memory");
        __syncthreads();
        // issue B chunk c+1 into the other stage (overlaps with compute below)
        if (c + 1 < nch) {
            #pragma unroll
            for (int h = 0; h < 2; h++)
                cpasync16(sBs + (uint32_t)((((st ^ 1) * 16 + brow[h]) * 128 + bc4[h]) * 4),
                          Bb + (size_t)(c + 1) * 16 * 256 + (size_t)brow[h] * 256 + bc4[h]);
            asm volatile("cp.async.commit_group;" ::: "memory");
        }
        #pragma unroll
        for (int k = 0; k < 16; k++) {
            float a[8], b[8];
            *(float4*)&a[0] = *(const float4*)&As[st][k][ty * 8];
            *(float4*)&a[4] = *(const float4*)&As[st][k][ty * 8 + 4];
            *(float4*)&b[0] = *(const float4*)&Bs[st][k][tx * 8];
            *(float4*)&b[4] = *(const float4*)&Bs[st][k][tx * 8 + 4];
            #pragma unroll
            for (int i = 0; i < 8; i++)
                #pragma unroll
                for (int j = 0; j < 8; j++) acc[i][j] += a[i] * b[j];
        }
        // no trailing sync needed: next iter's A-STS and B-cp.async target the
        // opposite stage; reads of that stage completed before this iter's sync.
    }

    #pragma unroll
    for (int i = 0; i < 8; i++) {
        float* Crow = C + (size_t)(bm * 128 + ty * 8 + i) * 256 + bn * 128 + tx * 8;
        *(float4*)&Crow[0] = make_float4(acc[i][0], acc[i][1], acc[i][2], acc[i][3]);
        *(float4*)&Crow[4] = make_float4(acc[i][4], acc[i][5], acc[i][6], acc[i][7]);
    }
}

// ---------------- prep kernels ----------------
__global__ void zero_f(float* p, int n) {
    int i = blockIdx.x * 256 + threadIdx.x;
    if (i < n) p[i] = 0.f;
}

__global__ void nan_copy(const float* __restrict__ x, float* __restrict__ h, int n) {
    int i = blockIdx.x * 256 + threadIdx.x;
    if (i < n) { float v = x[i]; h[i] = isnan(v) ? 0.f : v; }
}

__global__ void build_adj(const int* __restrict__ src, const int* __restrict__ dst,
                          int E, float* __restrict__ A) {
    int e = blockIdx.x * 256 + threadIdx.x;
    if (e >= E) return;
    int s = src[e], d = dst[e];
    int g = d >> 6;
    atomicAdd(&A[((size_t)g << 12) + ((size_t)(d & 63) << 6) + (s & 63)], 1.0f);
}

__global__ void norm_adj(float* __restrict__ A) {
    int row  = blockIdx.x * 8 + (threadIdx.x >> 5);
    int lane = threadIdx.x & 31;
    float* rp = A + (size_t)row * 64;
    float v0 = rp[lane], v1 = rp[lane + 32];
    float s = v0 + v1;
    #pragma unroll
    for (int o = 16; o > 0; o >>= 1) s += __shfl_xor_sync(0xffffffffu, s, o);
    float inv = 1.f / fmaxf(s, 1.f);
    rp[lane] = v0 * inv; rp[lane + 32] = v1 * inv;
}

// conv weight: planes[o][s*256+i] = split2(w[(o*256+i)*4 + s])
__global__ void cwsplit2(const float* __restrict__ w,
                         __nv_bfloat16* __restrict__ p0, __nv_bfloat16* __restrict__ p1) {
    int idx = blockIdx.x * 256 + threadIdx.x;
    if (idx >= 256 * 1024) return;
    int o = idx >> 10, k = idx & 1023;
    int s = k >> 8, i = k & 255;
    float v = w[((size_t)(o * 256 + i)) * 4 + s];
    __nv_bfloat16 h0 = __float2bfloat16(v);
    p0[idx] = h0;
    p1[idx] = __float2bfloat16(v - __bfloat162float(h0));
}

// ------------- SAGE combine (verbatim round-1: key-path, bit-exact) ---------
__global__ __launch_bounds__(256) void sage_combine(
    const float* __restrict__ HL, const float* __restrict__ HR,
    const float* __restrict__ bias, float* __restrict__ Hout,
    const float* __restrict__ Aadj)
{
    __shared__ float As[64][64];
    __shared__ float HLs[64][128];
    int g = blockIdx.x, t = threadIdx.x;
    const float* Ag = Aadj + ((size_t)g << 12);

    #pragma unroll
    for (int h = 0; h < 4; h++) {
        int idx = t + h * 256;
        int n = idx >> 4, k4 = (idx & 15) * 4;
        float4 v = *reinterpret_cast<const float4*>(Ag + (size_t)n * 64 + k4);
        As[k4 + 0][n] = v.x; As[k4 + 1][n] = v.y;
        As[k4 + 2][n] = v.z; As[k4 + 3][n] = v.w;
    }

    int ngrp = t >> 4;
    int cgrp = t & 15;

    for (int ch = 0; ch < 2; ch++) {
        __syncthreads();
        #pragma unroll
        for (int h = 0; h < 8; h++) {
            int idx = t + h * 256;
            int k = idx >> 5, c4 = (idx & 31) * 4;
            *reinterpret_cast<float4*>(&HLs[k][c4]) =
                *reinterpret_cast<const float4*>(HL + ((size_t)(g * 64 + k)) * HH + ch * 128 + c4);
        }
        __syncthreads();

        float acc[4][8];
        #pragma unroll
        for (int i = 0; i < 4; i++)
            #pragma unroll
            for (int j = 0; j < 8; j++) acc[i][j] = 0.f;

        #pragma unroll 4
        for (int k = 0; k < 64; k++) {
            float a[4], b[8];
            *reinterpret_cast<float4*>(&a[0]) = *reinterpret_cast<const float4*>(&As[k][ngrp * 4]);
            *reinterpret_cast<float4*>(&b[0]) = *reinterpret_cast<const float4*>(&HLs[k][cgrp * 8]);
            *reinterpret_cast<float4*>(&b[4]) = *reinterpret_cast<const float4*>(&HLs[k][cgrp * 8 + 4]);
            #pragma unroll
            for (int i = 0; i < 4; i++)
                #pragma unroll
                for (int j = 0; j < 8; j++) acc[i][j] += a[i] * b[j];
        }
        #pragma unroll
        for (int i = 0; i < 4; i++) {
            int n = ngrp * 4 + i;
            size_t base = ((size_t)(g * 64 + n)) * HH + ch * 128 + cgrp * 8;
            #pragma unroll
            for (int j = 0; j < 8; j++) {
                float v = acc[i][j] + bias[ch * 128 + cgrp * 8 + j] + HR[base + j];
                Hout[base + j] = fmaxf(v, 0.f);
            }
        }
    }
}

// ------------- SortPool: exact fp32 keys, emit bf16 split-2 topk planes -----
__global__ __launch_bounds__(256) void sort_topk2(
    const float* __restrict__ H,
    __nv_bfloat16* __restrict__ t0, __nv_bfloat16* __restrict__ t1)
{
    int g = blockIdx.x, t = threadIdx.x;
    __shared__ float keys[64];
    __shared__ int   sel[KSORT];
    if (t < 64) keys[t] = H[((size_t)(g * 64 + t)) * HH + 255];
    __syncthreads();
    if (t < 64) {
        float kv = keys[t];
        int r = 0;
        #pragma unroll
        for (int m = 0; m < 64; m++) {
            float km = keys[m];
            r += (km > kv) || (km == kv && m < t);
        }
        if (r < KSORT) sel[r] = t;
    }
    __syncthreads();
    for (int idx = t; idx < KSORT * HH; idx += 256) {
        int r = idx >> 8, c = idx & 255;
        float v = H[((size_t)(g * 64 + sel[r])) * HH + c];
        __nv_bfloat16 h0 = __float2bfloat16(v);
        size_t d = (size_t)g * KSORT * HH + idx;
        t0[d] = h0;
        t1[d] = __float2bfloat16(v - __bfloat162float(h0));
    }
}

// ============ conv1d as bf16 tensor-core GEMM (fused im2col) ================
// Y[m,o] = relu(bias[o] + sum_k A[m,k]*W[o,k]), m=(g,tp), k=(s,i), K=1024.
// 2-plane split, 3 products (a0b0+a0b1+a1b0): rel err ~2e-5, no sort impact.
#define CPROW_B   80
#define CPLANE_B  (128*CPROW_B)     // 10240
#define CSTAGE_B  (4*CPLANE_B)      // 40960: A0 A1 B0 B1
#define CSMZ      (2*CSTAGE_B)      // 81920

__global__ __launch_bounds__(256) void conv_tc(
    const __nv_bfloat16* __restrict__ T0, const __nv_bfloat16* __restrict__ T1,
    const __nv_bfloat16* __restrict__ W0, const __nv_bfloat16* __restrict__ W1,
    float* __restrict__ Y, const float* __restrict__ bias)
{
    extern __shared__ char smem[];
    const int t    = threadIdx.x;
    const int lane = t & 31;
    const int wid  = t >> 5;
    const int wm   = wid & 3;
    const int wn   = wid >> 2;
    const int m0   = blockIdx.y * 128;
    const int n0   = blockIdx.x * 128;
    const int lr   = lane >> 2;
    const int lc   = lane & 3;
    const int nch  = 32;            // K=1024, 32 k per chunk

    uint32_t sbase = smem_u32(smem);

    auto ld_stage = [&](int stage, int c) {
        uint32_t sb = sbase + stage * CSTAGE_B;
        int kt = c << 5;
        int sp = kt >> 8, ko = kt & 255;
        #pragma unroll
        for (int i = 0; i < 8; i++) {
            int idx = t + i * 256;          // 0..2047
            int pl  = idx >> 9;             // 0..3
            int rem = idx & 511;
            int row = rem >> 2, q = rem & 3;
            uint32_t dst = sb + pl * CPLANE_B + row * CPROW_B + q * 16;
            const __nv_bfloat16* src;
            if (pl < 2) {
                const __nv_bfloat16* P = (pl == 0) ? T0 : T1;
                int m = m0 + row;
                int g = m / 27, tp = m - g * 27;
                src = P + (size_t)((g * 30 + tp + sp) * 256 + ko) + q * 8;
            } else {
                const __nv_bfloat16* P = (pl == 2) ? W0 : W1;
                src = P + (size_t)(n0 + row) * 1024 + kt + q * 8;
            }
            cpasync16(dst, src);
        }
        asm volatile("cp.async.commit_group;" ::: "memory");
    };

    float acc[2][8][4];
    #pragma unroll
    for (int m = 0; m < 2; m++)
        #pragma unroll
        for (int j = 0; j < 8; j++)
            #pragma unroll
            for (int q = 0; q < 4; q++) acc[m][j][q] = 0.f;

    ld_stage(0, 0);
    ld_stage(1, 1);

    for (int c = 0; c < nch; c++) {
        if (c + 1 < nch) asm volatile("cp.async.wait_group 1;" ::: "memory");
        else             asm volatile("cp.async.wait_group 0;" ::: "memory");
        __syncthreads();

        const char* sb = smem + (c & 1) * CSTAGE_B;

        #pragma unroll
        for (int s = 0; s < 2; s++) {
            int kc = s * 32 + lc * 4;    // byte offset within 80B row
            uint32_t A0f[2][4], A1f[2][4];
            #pragma unroll
            for (int m = 0; m < 2; m++) {
                int r0 = (wm * 32 + m * 16 + lr) * CPROW_B;
                int r1 = r0 + 8 * CPROW_B;
                A0f[m][0] = *(const uint32_t*)(sb + r0 + kc);
                A0f[m][1] = *(const uint32_t*)(sb + r1 + kc);
                A0f[m][2] = *(const uint32_t*)(sb + r0 + kc + 16);
                A0f[m][3] = *(const uint32_t*)(sb + r1 + kc + 16);
                A1f[m][0] = *(const uint32_t*)(sb + CPLANE_B + r0 + kc);
                A1f[m][1] = *(const uint32_t*)(sb + CPLANE_B + r1 + kc);
                A1f[m][2] = *(const uint32_t*)(sb + CPLANE_B + r0 + kc + 16);
                A1f[m][3] = *(const uint32_t*)(sb + CPLANE_B + r1 + kc + 16);
            }
            #pragma unroll
            for (int j = 0; j < 8; j++) {
                int nr = (wn * 64 + j * 8 + lr) * CPROW_B;
                uint32_t b00 = *(const uint32_t*)(sb + 2*CPLANE_B + nr + kc);
                uint32_t b01 = *(const uint32_t*)(sb + 2*CPLANE_B + nr + kc + 16);
                uint32_t b10 = *(const uint32_t*)(sb + 3*CPLANE_B + nr + kc);
                uint32_t b11 = *(const uint32_t*)(sb + 3*CPLANE_B + nr + kc + 16);
                #pragma unroll
                for (int m = 0; m < 2; m++) {
                    mma16(acc[m][j], A0f[m][0], A0f[m][1], A0f[m][2], A0f[m][3], b00, b01);
                    mma16(acc[m][j], A0f[m][0], A0f[m][1], A0f[m][2], A0f[m][3], b10, b11);
                    mma16(acc[m][j], A1f[m][0], A1f[m][1], A1f[m][2], A1f[m][3], b00, b01);
                }
            }
        }
        if (c + 2 < nch) {
            __syncthreads();
            ld_stage(c & 1, c + 2);
        }
    }

    #pragma unroll
    for (int m = 0; m < 2; m++) {
        int row = m0 + wm * 32 + m * 16 + lr;
        #pragma unroll
        for (int j = 0; j < 8; j++) {
            int col = n0 + wn * 64 + j * 8 + 2 * lc;
            float b0 = bias[col], b1 = bias[col + 1];
            float2 v0 = make_float2(fmaxf(acc[m][j][0] + b0, 0.f),
                                    fmaxf(acc[m][j][1] + b1, 0.f));
            float2 v1 = make_float2(fmaxf(acc[m][j][2] + b0, 0.f),
                                    fmaxf(acc[m][j][3] + b1, 0.f));
            *(float2*)(Y + (size_t)row * 256 + col)       = v0;
            *(float2*)(Y + (size_t)(row + 8) * 256 + col) = v1;
        }
    }
}

// ------------- lin1 split-K GEMM (verbatim round-1) -------------------------
__global__ __launch_bounds__(256) void lin1_splitk(
    const float* __restrict__ Y, const float* __restrict__ W1,
    float* __restrict__ Zacc)
{
    __shared__ float As[16][128];
    __shared__ float Bs[16][128];
    int t  = threadIdx.x;
    int bn = blockIdx.x, bm = blockIdx.y, ts = blockIdx.z;
    int tx = t & 15, ty = t >> 4;

    float acc[8][8];
    #pragma unroll
    for (int i = 0; i < 8; i++)
        #pragma unroll
        for (int j = 0; j < 8; j++) acc[i][j] = 0.f;

    for (int kt = 0; kt < 256; kt += 16) {
        #pragma unroll
        for (int h = 0; h < 2; h++) {
            int idx = t + h * 256;
            int row = idx >> 2, c4 = (idx & 3) * 4;
            float4 v = *reinterpret_cast<const float4*>(
                Y + ((size_t)(bm * 128 + row) * LOUT + ts) * HH + kt + c4);
            As[c4 + 0][row] = v.x; As[c4 + 1][row] = v.y;
            As[c4 + 2][row] = v.z; As[c4 + 3][row] = v.w;
        }
        #pragma unroll
        for (int h = 0; h < 2; h++) {
            int idx = t + h * 256;
            int row = idx >> 5, c4 = (idx & 31) * 4;
            float4 v = *reinterpret_cast<const float4*>(
                W1 + ((size_t)(kt + row) * LOUT + ts) * HH + bn * 128 + c4);
            *reinterpret_cast<float4*>(&Bs[row][c4]) = v;
        }
        __syncthreads();
        #pragma unroll
        for (int k = 0; k < 16; k++) {
            float a[8], b[8];
            *reinterpret_cast<float4*>(&a[0]) = *reinterpret_cast<const float4*>(&As[k][ty * 8]);
            *reinterpret_cast<float4*>(&a[4]) = *reinterpret_cast<const float4*>(&As[k][ty * 8 + 4]);
            *reinterpret_cast<float4*>(&b[0]) = *reinterpret_cast<const float4*>(&Bs[k][tx * 8]);
            *reinterpret_cast<float4*>(&b[4]) = *reinterpret_cast<const float4*>(&Bs[k][tx * 8 + 4]);
            #pragma unroll
            for (int i = 0; i < 8; i++)
                #pragma unroll
                for (int j = 0; j < 8; j++) acc[i][j] += a[i] * b[j];
        }
        __syncthreads();
    }
    #pragma unroll
    for (int i = 0; i < 8; i++) {
        int m = bm * 128 + ty * 8 + i;
        #pragma unroll
        for (int j = 0; j < 8; j++)
            atomicAdd(&Zacc[(size_t)m * HH + bn * 128 + tx * 8 + j], acc[i][j]);
    }
}

// ------------- final MLP (verbatim round-1) ----------------------------------
__global__ __launch_bounds__(256) void mlp_kernel(
    const float* __restrict__ z1acc, const float* __restrict__ b1,
    const float* __restrict__ W2,   const float* __restrict__ b2,
    const float* __restrict__ W3,   const float* __restrict__ b3,
    float* __restrict__ out)
{
    int g = blockIdx.x, t = threadIdx.x;
    __shared__ float s1[256];
    __shared__ float s2[128];
    s1[t] = fmaxf(z1acc[(size_t)g * 256 + t] + b1[t], 0.f);
    __syncthreads();
    if (t < 128) {
        float acc = b2[t];
        #pragma unroll 8
        for (int k = 0; k < 256; k++) acc += s1[k] * W2[(size_t)k * 128 + t];
        s2[t] = fmaxf(acc, 0.f);
    }
    __syncthreads();
    if (t < 10) {
        float acc = b3[t];
        #pragma unroll
        for (int k = 0; k < 128; k++) acc += s2[k] * W3[(size_t)k * 10 + t];
        out[(size_t)g * 10 + t] = fmaxf(acc, 0.f);
    }
}

// ---------------- launch ----------------
extern "C" void kernel_launch(void* const* d_in, const int* in_sizes, int n_in,
                              void* d_out, int out_size)
{
    const float* x  = (const float*)d_in[0];
    const int*   ei = (const int*)  d_in[1];
    int E = in_sizes[1] / 2;
    const int* src = ei;
    const int* dst = ei + E;

    const float* wl[4] = {(const float*)d_in[3], (const float*)d_in[6],
                          (const float*)d_in[9], (const float*)d_in[12]};
    const float* wr[4] = {(const float*)d_in[4], (const float*)d_in[7],
                          (const float*)d_in[10], (const float*)d_in[13]};
    const float* sb[4] = {(const float*)d_in[5], (const float*)d_in[8],
                          (const float*)d_in[11], (const float*)d_in[14]};
    const float* convw = (const float*)d_in[15];
    const float* convb = (const float*)d_in[16];
    const float* l1w   = (const float*)d_in[17];
    const float* l1b   = (const float*)d_in[18];
    const float* l2w   = (const float*)d_in[19];
    const float* l2b   = (const float*)d_in[20];
    const float* ow    = (const float*)d_in[21];
    const float* ob    = (const float*)d_in[22];

    float *pA, *pH0, *pH1, *pHL, *pHR, *pYc, *pZ1;
    __nv_bfloat16 *pt0, *pt1, *pc0, *pc1;
    cudaGetSymbolAddress((void**)&pA,  g_A);
    cudaGetSymbolAddress((void**)&pH0, g_h0);
    cudaGetSymbolAddress((void**)&pH1, g_h1);
    cudaGetSymbolAddress((void**)&pHL, g_HL);
    cudaGetSymbolAddress((void**)&pHR, g_HR);
    cudaGetSymbolAddress((void**)&pYc, g_yc);
    cudaGetSymbolAddress((void**)&pZ1, g_z1);
    cudaGetSymbolAddress((void**)&pt0, g_t0);
    cudaGetSymbolAddress((void**)&pt1, g_t1);
    cudaGetSymbolAddress((void**)&pc0, g_c0);
    cudaGetSymbolAddress((void**)&pc1, g_c1);

    cudaFuncSetAttribute(conv_tc, cudaFuncAttributeMaxDynamicSharedMemorySize, CSMZ);

    // preprocessing
    zero_f<<<(NB*PP*PP + 255)/256, 256>>>(pA, NB*PP*PP);
    build_adj<<<(E + 255)/256, 256>>>(src, dst, E, pA);
    norm_adj<<<NN/8, 256>>>(pA);
    nan_copy<<<(NN*FF + 255)/256, 256>>>(x, pH0, NN*FF);
    zero_f<<<(NB*HH + 255)/256, 256>>>(pZ1, NB*HH);
    cwsplit2<<<(256*1024 + 255)/256, 256>>>(convw, pc0, pc1);

    // 4 SAGE layers — fp32 FFMA, bit-identical FP order to the passing R1 run
    float* hc = pH0;
    float* hn = pH1;
    for (int l = 0; l < 4; l++) {
        int K = (l == 0) ? FF : HH;
        gemm_f32ex<<<dim3(2, NN/128), 256>>>(hc, wl[l], pHL, K);
        gemm_f32ex<<<dim3(2, NN/128), 256>>>(hc, wr[l], pHR, K);
        sage_combine<<<NB, 256>>>(pHL, pHR, sb[l], hn, pA);
        float* tmp = hc; hc = hn; hn = tmp;
    }

    // SortPool (exact fp32 keys) -> conv1d on tensor cores -> lin1 -> MLP
    sort_topk2<<<NB, 256>>>(hc, pt0, pt1);
    conv_tc<<<dim3(2, MCONV/128), 256, CSMZ>>>(pt0, pt1, pc0, pc1, pYc, convb);
    lin1_splitk<<<dim3(2, 4, LOUT), 256>>>(pYc, l1w, pZ1);
    mlp_kernel<<<NB, 256>>>(pZ1, l1b, l2w, l2b, ow, ob, (float*)d_out);
}

// round 6
// speedup vs baseline: 1.3828x; 1.0470x over previous
#include <cuda_runtime.h>
#include <cuda_bf16.h>
#include <math.h>
#include <stdint.h>

// ---------------- problem constants ----------------
#define NB       512
#define PP       64
#define NN       (NB*PP)      // 32768
#define FF       128
#define HH       256
#define KSORT    30
#define LOUT     27
#define MCONV    (NB*LOUT)    // 13824 = 108*128

// ---------------- static scratch ----------------
__device__ __align__(16) float g_A  [NB*PP*PP];   // normalized adjacency
__device__ __align__(16) float g_h0 [NN*HH];      // activations ping
__device__ __align__(16) float g_h1 [NN*HH];      // pong
__device__ __align__(16) float g_HL [NN*HH];
__device__ __align__(16) float g_HR [NN*HH];
__device__ __align__(16) float g_yc [MCONV*HH];
__device__ __align__(16) float g_z1 [NB*HH];
// bf16 split planes (conv path only — not key-relevant)
__device__ __align__(16) __nv_bfloat16 g_t0[NB*KSORT*HH], g_t1[NB*KSORT*HH];
__device__ __align__(16) __nv_bfloat16 g_c0[HH*1024],     g_c1[HH*1024];

// ---------------- helpers ----------------
__device__ __forceinline__ uint32_t smem_u32(const void* p) {
    uint32_t a;
    asm("{ .reg .u64 t; cvta.to.shared.u64 t, %1; cvt.u32.u64 %0, t; }" : "=r"(a) : "l"(p));
    return a;
}
__device__ __forceinline__ void cpasync16(uint32_t dst, const void* src) {
    asm volatile("cp.async.cg.shared.global [%0], [%1], 16;" :: "r"(dst), "l"(src));
}
__device__ __forceinline__ void mma16(float* d, uint32_t a0, uint32_t a1,
                                      uint32_t a2, uint32_t a3,
                                      uint32_t b0, uint32_t b1) {
    asm volatile(
        "mma.sync.aligned.m16n8k16.row.col.f32.bf16.bf16.f32 "
        "{%0,%1,%2,%3}, {%4,%5,%6,%7}, {%8,%9}, {%0,%1,%2,%3};"
        : "+f"(d[0]), "+f"(d[1]), "+f"(d[2]), "+f"(d[3])
        : "r"(a0), "r"(a1), "r"(a2), "r"(a3), "r"(b0), "r"(b1));
}

// ====== SAGE dual GEMM: HL = A@Bl, HR = A@Br, bit-identical FP order ========
// BM=128, BN=64, BK=16, 256 threads, 8x4 per thread. grid (8, M/128):
// blockIdx.x = sel*4 + bn. Per-output FP chain: acc += a*b, k ascending —
// identical to R1/R5. Fine-grained 2048-CTA grid kills wave-quantization tails.
__global__ __launch_bounds__(256, 3) void gemm_dual(
    const float* __restrict__ A,
    const float* __restrict__ Bl, const float* __restrict__ Br,
    float* __restrict__ Cl, float* __restrict__ Cr, int K)
{
    __shared__ float As[2][16][128];
    __shared__ float Bs[2][16][64];
    const int t   = threadIdx.x;
    const int bn  = blockIdx.x & 3;
    const int sel = blockIdx.x >> 2;
    const int bm  = blockIdx.y;
    const int tx  = t & 15, ty = t >> 4;
    const float* B = sel ? Br : Bl;
    float*       C = sel ? Cr : Cl;
    const float* Ab = A + (size_t)bm * 128 * K;
    const float* Bb = B + bn * 64;
    const int nch = K >> 4;

    int arow[2], ak4[2];
    #pragma unroll
    for (int h = 0; h < 2; h++) {
        int idx = t + h * 256;
        arow[h] = idx >> 2;  ak4[h] = (idx & 3) * 4;
    }
    const int brow = t >> 4;          // 0..15
    const int bc4  = (t & 15) * 4;    // 0..60
    uint32_t sBs = smem_u32(Bs);

    // prefetch A chunk 0 into regs; cp.async B chunk 0 into stage 0
    float4 apref[2];
    #pragma unroll
    for (int h = 0; h < 2; h++)
        apref[h] = *(const float4*)(Ab + (size_t)arow[h] * K + ak4[h]);
    cpasync16(sBs + (uint32_t)((brow * 64 + bc4) * 4),
              Bb + (size_t)brow * 256 + bc4);
    asm volatile("cp.async.commit_group;" ::: "memory");

    float acc[8][4];
    #pragma unroll
    for (int i = 0; i < 8; i++)
        #pragma unroll
        for (int j = 0; j < 4; j++) acc[i][j] = 0.f;

    for (int c = 0; c < nch; c++) {
        const int st = c & 1;
        // stage A chunk c into smem (transposed)
        #pragma unroll
        for (int h = 0; h < 2; h++) {
            As[st][ak4[h] + 0][arow[h]] = apref[h].x;
            As[st][ak4[h] + 1][arow[h]] = apref[h].y;
            As[st][ak4[h] + 2][arow[h]] = apref[h].z;
            As[st][ak4[h] + 3][arow[h]] = apref[h].w;
        }
        // prefetch A chunk c+1
        if (c + 1 < nch) {
            #pragma unroll
            for (int h = 0; h < 2; h++)
                apref[h] = *(const float4*)(Ab + (size_t)arow[h] * K + (c + 1) * 16 + ak4[h]);
        }
        asm volatile("cp.async.wait_group 0;" ::: "memory");
        __syncthreads();
        // issue B chunk c+1 into the other stage (overlaps with compute)
        if (c + 1 < nch) {
            cpasync16(sBs + (uint32_t)(((((st ^ 1) * 16) + brow) * 64 + bc4) * 4),
                      Bb + (size_t)(c + 1) * 16 * 256 + (size_t)brow * 256 + bc4);
            asm volatile("cp.async.commit_group;" ::: "memory");
        }
        #pragma unroll
        for (int k = 0; k < 16; k++) {
            float a[8], b[4];
            *(float4*)&a[0] = *(const float4*)&As[st][k][ty * 8];
            *(float4*)&a[4] = *(const float4*)&As[st][k][ty * 8 + 4];
            *(float4*)&b[0] = *(const float4*)&Bs[st][k][tx * 4];
            #pragma unroll
            for (int i = 0; i < 8; i++)
                #pragma unroll
                for (int j = 0; j < 4; j++) acc[i][j] += a[i] * b[j];
        }
    }

    #pragma unroll
    for (int i = 0; i < 8; i++) {
        float* Crow = C + (size_t)(bm * 128 + ty * 8 + i) * 256 + bn * 64 + tx * 4;
        *(float4*)Crow = make_float4(acc[i][0], acc[i][1], acc[i][2], acc[i][3]);
    }
}

// ---------------- prep kernels ----------------
__global__ void zero_f(float* p, int n) {
    int i = blockIdx.x * 256 + threadIdx.x;
    if (i < n) p[i] = 0.f;
}

__global__ void nan_copy(const float* __restrict__ x, float* __restrict__ h, int n) {
    int i = blockIdx.x * 256 + threadIdx.x;
    if (i < n) { float v = x[i]; h[i] = isnan(v) ? 0.f : v; }
}

__global__ void build_adj(const int* __restrict__ src, const int* __restrict__ dst,
                          int E, float* __restrict__ A) {
    int e = blockIdx.x * 256 + threadIdx.x;
    if (e >= E) return;
    int s = src[e], d = dst[e];
    int g = d >> 6;
    atomicAdd(&A[((size_t)g << 12) + ((size_t)(d & 63) << 6) + (s & 63)], 1.0f);
}

__global__ void norm_adj(float* __restrict__ A) {
    int row  = blockIdx.x * 8 + (threadIdx.x >> 5);
    int lane = threadIdx.x & 31;
    float* rp = A + (size_t)row * 64;
    float v0 = rp[lane], v1 = rp[lane + 32];
    float s = v0 + v1;
    #pragma unroll
    for (int o = 16; o > 0; o >>= 1) s += __shfl_xor_sync(0xffffffffu, s, o);
    float inv = 1.f / fmaxf(s, 1.f);
    rp[lane] = v0 * inv; rp[lane + 32] = v1 * inv;
}

// conv weight: planes[o][s*256+i] = split2(w[(o*256+i)*4 + s])
__global__ void cwsplit2(const float* __restrict__ w,
                         __nv_bfloat16* __restrict__ p0, __nv_bfloat16* __restrict__ p1) {
    int idx = blockIdx.x * 256 + threadIdx.x;
    if (idx >= 256 * 1024) return;
    int o = idx >> 10, k = idx & 1023;
    int s = k >> 8, i = k & 255;
    float v = w[((size_t)(o * 256 + i)) * 4 + s];
    __nv_bfloat16 h0 = __float2bfloat16(v);
    p0[idx] = h0;
    p1[idx] = __float2bfloat16(v - __bfloat162float(h0));
}

// ------------- SAGE combine (verbatim: key-path, bit-exact) -----------------
__global__ __launch_bounds__(256) void sage_combine(
    const float* __restrict__ HL, const float* __restrict__ HR,
    const float* __restrict__ bias, float* __restrict__ Hout,
    const float* __restrict__ Aadj)
{
    __shared__ float As[64][64];
    __shared__ float HLs[64][128];
    int g = blockIdx.x, t = threadIdx.x;
    const float* Ag = Aadj + ((size_t)g << 12);

    #pragma unroll
    for (int h = 0; h < 4; h++) {
        int idx = t + h * 256;
        int n = idx >> 4, k4 = (idx & 15) * 4;
        float4 v = *reinterpret_cast<const float4*>(Ag + (size_t)n * 64 + k4);
        As[k4 + 0][n] = v.x; As[k4 + 1][n] = v.y;
        As[k4 + 2][n] = v.z; As[k4 + 3][n] = v.w;
    }

    int ngrp = t >> 4;
    int cgrp = t & 15;

    for (int ch = 0; ch < 2; ch++) {
        __syncthreads();
        #pragma unroll
        for (int h = 0; h < 8; h++) {
            int idx = t + h * 256;
            int k = idx >> 5, c4 = (idx & 31) * 4;
            *reinterpret_cast<float4*>(&HLs[k][c4]) =
                *reinterpret_cast<const float4*>(HL + ((size_t)(g * 64 + k)) * HH + ch * 128 + c4);
        }
        __syncthreads();

        float acc[4][8];
        #pragma unroll
        for (int i = 0; i < 4; i++)
            #pragma unroll
            for (int j = 0; j < 8; j++) acc[i][j] = 0.f;

        #pragma unroll 4
        for (int k = 0; k < 64; k++) {
            float a[4], b[8];
            *reinterpret_cast<float4*>(&a[0]) = *reinterpret_cast<const float4*>(&As[k][ngrp * 4]);
            *reinterpret_cast<float4*>(&b[0]) = *reinterpret_cast<const float4*>(&HLs[k][cgrp * 8]);
            *reinterpret_cast<float4*>(&b[4]) = *reinterpret_cast<const float4*>(&HLs[k][cgrp * 8 + 4]);
            #pragma unroll
            for (int i = 0; i < 4; i++)
                #pragma unroll
                for (int j = 0; j < 8; j++) acc[i][j] += a[i] * b[j];
        }
        #pragma unroll
        for (int i = 0; i < 4; i++) {
            int n = ngrp * 4 + i;
            size_t base = ((size_t)(g * 64 + n)) * HH + ch * 128 + cgrp * 8;
            #pragma unroll
            for (int j = 0; j < 8; j++) {
                float v = acc[i][j] + bias[ch * 128 + cgrp * 8 + j] + HR[base + j];
                Hout[base + j] = fmaxf(v, 0.f);
            }
        }
    }
}

// ------------- SortPool: exact fp32 keys, emit bf16 split-2 topk planes -----
__global__ __launch_bounds__(256) void sort_topk2(
    const float* __restrict__ H,
    __nv_bfloat16* __restrict__ t0, __nv_bfloat16* __restrict__ t1)
{
    int g = blockIdx.x, t = threadIdx.x;
    __shared__ float keys[64];
    __shared__ int   sel[KSORT];
    if (t < 64) keys[t] = H[((size_t)(g * 64 + t)) * HH + 255];
    __syncthreads();
    if (t < 64) {
        float kv = keys[t];
        int r = 0;
        #pragma unroll
        for (int m = 0; m < 64; m++) {
            float km = keys[m];
            r += (km > kv) || (km == kv && m < t);
        }
        if (r < KSORT) sel[r] = t;
    }
    __syncthreads();
    for (int idx = t; idx < KSORT * HH; idx += 256) {
        int r = idx >> 8, c = idx & 255;
        float v = H[((size_t)(g * 64 + sel[r])) * HH + c];
        __nv_bfloat16 h0 = __float2bfloat16(v);
        size_t d = (size_t)g * KSORT * HH + idx;
        t0[d] = h0;
        t1[d] = __float2bfloat16(v - __bfloat162float(h0));
    }
}

// ============ conv1d as bf16 tensor-core GEMM (fused im2col) ================
#define CPROW_B   80
#define CPLANE_B  (128*CPROW_B)     // 10240
#define CSTAGE_B  (4*CPLANE_B)      // 40960: A0 A1 B0 B1
#define CSMZ      (2*CSTAGE_B)      // 81920

__global__ __launch_bounds__(256) void conv_tc(
    const __nv_bfloat16* __restrict__ T0, const __nv_bfloat16* __restrict__ T1,
    const __nv_bfloat16* __restrict__ W0, const __nv_bfloat16* __restrict__ W1,
    float* __restrict__ Y, const float* __restrict__ bias)
{
    extern __shared__ char smem[];
    const int t    = threadIdx.x;
    const int lane = t & 31;
    const int wid  = t >> 5;
    const int wm   = wid & 3;
    const int wn   = wid >> 2;
    const int m0   = blockIdx.y * 128;
    const int n0   = blockIdx.x * 128;
    const int lr   = lane >> 2;
    const int lc   = lane & 3;
    const int nch  = 32;            // K=1024, 32 k per chunk

    uint32_t sbase = smem_u32(smem);

    auto ld_stage = [&](int stage, int c) {
        uint32_t sb = sbase + stage * CSTAGE_B;
        int kt = c << 5;
        int sp = kt >> 8, ko = kt & 255;
        #pragma unroll
        for (int i = 0; i < 8; i++) {
            int idx = t + i * 256;          // 0..2047
            int pl  = idx >> 9;             // 0..3
            int rem = idx & 511;
            int row = rem >> 2, q = rem & 3;
            uint32_t dst = sb + pl * CPLANE_B + row * CPROW_B + q * 16;
            const __nv_bfloat16* src;
            if (pl < 2) {
                const __nv_bfloat16* P = (pl == 0) ? T0 : T1;
                int m = m0 + row;
                int g = m / 27, tp = m - g * 27;
                src = P + (size_t)((g * 30 + tp + sp) * 256 + ko) + q * 8;
            } else {
                const __nv_bfloat16* P = (pl == 2) ? W0 : W1;
                src = P + (size_t)(n0 + row) * 1024 + kt + q * 8;
            }
            cpasync16(dst, src);
        }
        asm volatile("cp.async.commit_group;" ::: "memory");
    };

    float acc[2][8][4];
    #pragma unroll
    for (int m = 0; m < 2; m++)
        #pragma unroll
        for (int j = 0; j < 8; j++)
            #pragma unroll
            for (int q = 0; q < 4; q++) acc[m][j][q] = 0.f;

    ld_stage(0, 0);
    ld_stage(1, 1);

    for (int c = 0; c < nch; c++) {
        if (c + 1 < nch) asm volatile("cp.async.wait_group 1;" ::: "memory");
        else             asm volatile("cp.async.wait_group 0;" ::: "memory");
        __syncthreads();

        const char* sb = smem + (c & 1) * CSTAGE_B;

        #pragma unroll
        for (int s = 0; s < 2; s++) {
            int kc = s * 32 + lc * 4;
            uint32_t A0f[2][4], A1f[2][4];
            #pragma unroll
            for (int m = 0; m < 2; m++) {
                int r0 = (wm * 32 + m * 16 + lr) * CPROW_B;
                int r1 = r0 + 8 * CPROW_B;
                A0f[m][0] = *(const uint32_t*)(sb + r0 + kc);
                A0f[m][1] = *(const uint32_t*)(sb + r1 + kc);
                A0f[m][2] = *(const uint32_t*)(sb + r0 + kc + 16);
                A0f[m][3] = *(const uint32_t*)(sb + r1 + kc + 16);
                A1f[m][0] = *(const uint32_t*)(sb + CPLANE_B + r0 + kc);
                A1f[m][1] = *(const uint32_t*)(sb + CPLANE_B + r1 + kc);
                A1f[m][2] = *(const uint32_t*)(sb + CPLANE_B + r0 + kc + 16);
                A1f[m][3] = *(const uint32_t*)(sb + CPLANE_B + r1 + kc + 16);
            }
            #pragma unroll
            for (int j = 0; j < 8; j++) {
                int nr = (wn * 64 + j * 8 + lr) * CPROW_B;
                uint32_t b00 = *(const uint32_t*)(sb + 2*CPLANE_B + nr + kc);
                uint32_t b01 = *(const uint32_t*)(sb + 2*CPLANE_B + nr + kc + 16);
                uint32_t b10 = *(const uint32_t*)(sb + 3*CPLANE_B + nr + kc);
                uint32_t b11 = *(const uint32_t*)(sb + 3*CPLANE_B + nr + kc + 16);
                #pragma unroll
                for (int m = 0; m < 2; m++) {
                    mma16(acc[m][j], A0f[m][0], A0f[m][1], A0f[m][2], A0f[m][3], b00, b01);
                    mma16(acc[m][j], A0f[m][0], A0f[m][1], A0f[m][2], A0f[m][3], b10, b11);
                    mma16(acc[m][j], A1f[m][0], A1f[m][1], A1f[m][2], A1f[m][3], b00, b01);
                }
            }
        }
        if (c + 2 < nch) {
            __syncthreads();
            ld_stage(c & 1, c + 2);
        }
    }

    #pragma unroll
    for (int m = 0; m < 2; m++) {
        int row = m0 + wm * 32 + m * 16 + lr;
        #pragma unroll
        for (int j = 0; j < 8; j++) {
            int col = n0 + wn * 64 + j * 8 + 2 * lc;
            float b0 = bias[col], b1 = bias[col + 1];
            float2 v0 = make_float2(fmaxf(acc[m][j][0] + b0, 0.f),
                                    fmaxf(acc[m][j][1] + b1, 0.f));
            float2 v1 = make_float2(fmaxf(acc[m][j][2] + b0, 0.f),
                                    fmaxf(acc[m][j][3] + b1, 0.f));
            *(float2*)(Y + (size_t)row * 256 + col)       = v0;
            *(float2*)(Y + (size_t)(row + 8) * 256 + col) = v1;
        }
    }
}

// ------------- lin1 split-K GEMM (verbatim) ---------------------------------
__global__ __launch_bounds__(256) void lin1_splitk(
    const float* __restrict__ Y, const float* __restrict__ W1,
    float* __restrict__ Zacc)
{
    __shared__ float As[16][128];
    __shared__ float Bs[16][128];
    int t  = threadIdx.x;
    int bn = blockIdx.x, bm = blockIdx.y, ts = blockIdx.z;
    int tx = t & 15, ty = t >> 4;

    float acc[8][8];
    #pragma unroll
    for (int i = 0; i < 8; i++)
        #pragma unroll
        for (int j = 0; j < 8; j++) acc[i][j] = 0.f;

    for (int kt = 0; kt < 256; kt += 16) {
        #pragma unroll
        for (int h = 0; h < 2; h++) {
            int idx = t + h * 256;
            int row = idx >> 2, c4 = (idx & 3) * 4;
            float4 v = *reinterpret_cast<const float4*>(
                Y + ((size_t)(bm * 128 + row) * LOUT + ts) * HH + kt + c4);
            As[c4 + 0][row] = v.x; As[c4 + 1][row] = v.y;
            As[c4 + 2][row] = v.z; As[c4 + 3][row] = v.w;
        }
        #pragma unroll
        for (int h = 0; h < 2; h++) {
            int idx = t + h * 256;
            int row = idx >> 5, c4 = (idx & 31) * 4;
            float4 v = *reinterpret_cast<const float4*>(
                W1 + ((size_t)(kt + row) * LOUT + ts) * HH + bn * 128 + c4);
            *reinterpret_cast<float4*>(&Bs[row][c4]) = v;
        }
        __syncthreads();
        #pragma unroll
        for (int k = 0; k < 16; k++) {
            float a[8], b[8];
            *reinterpret_cast<float4*>(&a[0]) = *reinterpret_cast<const float4*>(&As[k][ty * 8]);
            *reinterpret_cast<float4*>(&a[4]) = *reinterpret_cast<const float4*>(&As[k][ty * 8 + 4]);
            *reinterpret_cast<float4*>(&b[0]) = *reinterpret_cast<const float4*>(&Bs[k][tx * 8]);
            *reinterpret_cast<float4*>(&b[4]) = *reinterpret_cast<const float4*>(&Bs[k][tx * 8 + 4]);
            #pragma unroll
            for (int i = 0; i < 8; i++)
                #pragma unroll
                for (int j = 0; j < 8; j++) acc[i][j] += a[i] * b[j];
        }
        __syncthreads();
    }
    #pragma unroll
    for (int i = 0; i < 8; i++) {
        int m = bm * 128 + ty * 8 + i;
        #pragma unroll
        for (int j = 0; j < 8; j++)
            atomicAdd(&Zacc[(size_t)m * HH + bn * 128 + tx * 8 + j], acc[i][j]);
    }
}

// ------------- final MLP (verbatim) ------------------------------------------
__global__ __launch_bounds__(256) void mlp_kernel(
    const float* __restrict__ z1acc, const float* __restrict__ b1,
    const float* __restrict__ W2,   const float* __restrict__ b2,
    const float* __restrict__ W3,   const float* __restrict__ b3,
    float* __restrict__ out)
{
    int g = blockIdx.x, t = threadIdx.x;
    __shared__ float s1[256];
    __shared__ float s2[128];
    s1[t] = fmaxf(z1acc[(size_t)g * 256 + t] + b1[t], 0.f);
    __syncthreads();
    if (t < 128) {
        float acc = b2[t];
        #pragma unroll 8
        for (int k = 0; k < 256; k++) acc += s1[k] * W2[(size_t)k * 128 + t];
        s2[t] = fmaxf(acc, 0.f);
    }
    __syncthreads();
    if (t < 10) {
        float acc = b3[t];
        #pragma unroll
        for (int k = 0; k < 128; k++) acc += s2[k] * W3[(size_t)k * 10 + t];
        out[(size_t)g * 10 + t] = fmaxf(acc, 0.f);
    }
}

// ---------------- launch ----------------
extern "C" void kernel_launch(void* const* d_in, const int* in_sizes, int n_in,
                              void* d_out, int out_size)
{
    const float* x  = (const float*)d_in[0];
    const int*   ei = (const int*)  d_in[1];
    int E = in_sizes[1] / 2;
    const int* src = ei;
    const int* dst = ei + E;

    const float* wl[4] = {(const float*)d_in[3], (const float*)d_in[6],
                          (const float*)d_in[9], (const float*)d_in[12]};
    const float* wr[4] = {(const float*)d_in[4], (const float*)d_in[7],
                          (const float*)d_in[10], (const float*)d_in[13]};
    const float* sb[4] = {(const float*)d_in[5], (const float*)d_in[8],
                          (const float*)d_in[11], (const float*)d_in[14]};
    const float* convw = (const float*)d_in[15];
    const float* convb = (const float*)d_in[16];
    const float* l1w   = (const float*)d_in[17];
    const float* l1b   = (const float*)d_in[18];
    const float* l2w   = (const float*)d_in[19];
    const float* l2b   = (const float*)d_in[20];
    const float* ow    = (const float*)d_in[21];
    const float* ob    = (const float*)d_in[22];

    float *pA, *pH0, *pH1, *pHL, *pHR, *pYc, *pZ1;
    __nv_bfloat16 *pt0, *pt1, *pc0, *pc1;
    cudaGetSymbolAddress((void**)&pA,  g_A);
    cudaGetSymbolAddress((void**)&pH0, g_h0);
    cudaGetSymbolAddress((void**)&pH1, g_h1);
    cudaGetSymbolAddress((void**)&pHL, g_HL);
    cudaGetSymbolAddress((void**)&pHR, g_HR);
    cudaGetSymbolAddress((void**)&pYc, g_yc);
    cudaGetSymbolAddress((void**)&pZ1, g_z1);
    cudaGetSymbolAddress((void**)&pt0, g_t0);
    cudaGetSymbolAddress((void**)&pt1, g_t1);
    cudaGetSymbolAddress((void**)&pc0, g_c0);
    cudaGetSymbolAddress((void**)&pc1, g_c1);

    cudaFuncSetAttribute(conv_tc, cudaFuncAttributeMaxDynamicSharedMemorySize, CSMZ);

    // preprocessing
    zero_f<<<(NB*PP*PP + 255)/256, 256>>>(pA, NB*PP*PP);
    build_adj<<<(E + 255)/256, 256>>>(src, dst, E, pA);
    norm_adj<<<NN/8, 256>>>(pA);
    nan_copy<<<(NN*FF + 255)/256, 256>>>(x, pH0, NN*FF);
    zero_f<<<(NB*HH + 255)/256, 256>>>(pZ1, NB*HH);
    cwsplit2<<<(256*1024 + 255)/256, 256>>>(convw, pc0, pc1);

    // 4 SAGE layers — fp32 FFMA, bit-identical FP order; dual GEMM per layer
    float* hc = pH0;
    float* hn = pH1;
    for (int l = 0; l < 4; l++) {
        int K = (l == 0) ? FF : HH;
        gemm_dual<<<dim3(8, NN/128), 256>>>(hc, wl[l], wr[l], pHL, pHR, K);
        sage_combine<<<NB, 256>>>(pHL, pHR, sb[l], hn, pA);
        float* tmp = hc; hc = hn; hn = tmp;
    }

    // SortPool (exact fp32 keys) -> conv1d on tensor cores -> lin1 -> MLP
    sort_topk2<<<NB, 256>>>(hc, pt0, pt1);
    conv_tc<<<dim3(2, MCONV/128), 256, CSMZ>>>(pt0, pt1, pc0, pc1, pYc, convb);
    lin1_splitk<<<dim3(2, 4, LOUT), 256>>>(pYc, l1w, pZ1);
    mlp_kernel<<<NB, 256>>>(pZ1, l1b, l2w, l2b, ow, ob, (float*)d_out);
}